// round 1
// baseline (speedup 1.0000x reference)
#include <cuda_runtime.h>

// Problem capacities (compile-time scratch sizing; runtime sizes from in_sizes)
#define E_CAP 100000
#define M_CAP 1000000

// -------- device scratch (no allocations allowed) --------
__device__ float    g_Vh[(size_t)E_CAP * 128];   // V projection [E,128]
__device__ float    g_kA[E_CAP * 8];             // per-edge per-head K score
__device__ unsigned g_maxk[E_CAP * 8];           // encoded segment max
__device__ float    g_denom[E_CAP * 8];          // softmax denominators
__device__ float    g_wkAT[8 * 128];             // pre-contracted Wk·Aw, [h][k]
__device__ float    g_bkA[8];                    // pre-contracted bk·Aw
__device__ int      g_idx64;                     // 1 if edge_edge_index is int64

// monotone float<->uint encoding for atomicMax on floats
__device__ __forceinline__ unsigned enc_f(float f) {
    unsigned b = __float_as_uint(f);
    return (b & 0x80000000u) ? ~b : (b | 0x80000000u);
}
__device__ __forceinline__ float dec_f(unsigned u) {
    unsigned b = (u & 0x80000000u) ? (u ^ 0x80000000u) : ~u;
    return __uint_as_float(b);
}
__device__ __forceinline__ int ld_idx(const void* idx, long long pos, int is64) {
    return is64 ? (int)((const long long*)idx)[pos] : ((const int*)idx)[pos];
}

// -------- K0: pre-contract Wk with Aw (Q projection is algebraically dead) ----
__global__ void prep_kernel(const float* __restrict__ Wk, const float* __restrict__ bk,
                            const float* __restrict__ Aw) {
    int k = threadIdx.x;
    if (k < 128) {
        #pragma unroll
        for (int h = 0; h < 8; h++) {
            float s = 0.f;
            #pragma unroll
            for (int d = 0; d < 16; d++) s += Wk[k * 128 + h * 16 + d] * Aw[d * 8 + h];
            g_wkAT[h * 128 + k] = s;
        }
    }
    if (k < 8) {
        float s = 0.f;
        #pragma unroll
        for (int d = 0; d < 16; d++) s += bk[k * 16 + d] * Aw[d * 8 + k];
        g_bkA[k] = s;
    }
}

// -------- K0b: detect int64 vs int32 index dtype on-device ----
__global__ void detect_kernel(const void* __restrict__ idx, int E) {
    if (threadIdx.x == 0 && blockIdx.x == 0) {
        const long long* p = (const long long*)idx;
        int ok = 1;
        for (int i = 0; i < 64; i++) {
            long long v = p[i];
            if (v < 0 || v >= (long long)E) { ok = 0; break; }
        }
        g_idx64 = ok;
    }
}

// -------- K1: Vh = edge_attr @ Wv + bv  (M=E, N=128, K=128 fp32 tiled GEMM) ----
__global__ void __launch_bounds__(256) gemm_vh_kernel(
    const float* __restrict__ A, const float* __restrict__ B,
    const float* __restrict__ bias, int Mrows)
{
    __shared__ float As[16][68];  // [kk][row], padded
    __shared__ float Bs[16][64];  // [kk][col]
    const int t  = threadIdx.x;
    const int tx = t & 15, ty = t >> 4;
    const int row0 = blockIdx.y * 64;
    const int col0 = blockIdx.x * 64;
    float acc[4][4] = {};

    for (int k0 = 0; k0 < 128; k0 += 16) {
        {   // A tile: 64 rows x 16 k
            int kk = t & 15, r = t >> 4;
            #pragma unroll
            for (int p = 0; p < 4; p++) {
                int row = row0 + r + p * 16;
                As[kk][r + p * 16] = (row < Mrows) ? A[(size_t)row * 128 + k0 + kk] : 0.f;
            }
        }
        {   // B tile: 16 k x 64 cols (float4)
            int kk = t >> 4, c4 = (t & 15) * 4;
            *(float4*)&Bs[kk][c4] = *(const float4*)(B + (size_t)(k0 + kk) * 128 + col0 + c4);
        }
        __syncthreads();
        #pragma unroll
        for (int kk = 0; kk < 16; kk++) {
            float a[4], b[4];
            #pragma unroll
            for (int i = 0; i < 4; i++) a[i] = As[kk][ty * 4 + i];
            #pragma unroll
            for (int j = 0; j < 4; j++) b[j] = Bs[kk][tx * 4 + j];
            #pragma unroll
            for (int i = 0; i < 4; i++)
                #pragma unroll
                for (int j = 0; j < 4; j++)
                    acc[i][j] += a[i] * b[j];
        }
        __syncthreads();
    }
    #pragma unroll
    for (int i = 0; i < 4; i++) {
        int row = row0 + ty * 4 + i;
        if (row >= Mrows) continue;
        #pragma unroll
        for (int j = 0; j < 4; j++) {
            int col = col0 + tx * 4 + j;
            g_Vh[(size_t)row * 128 + col] = acc[i][j] + bias[col];
        }
    }
}

// -------- K2: kA[e,h] = edge_attr[e] . wkAT[h] + bkA[h]  (warp per row) ----
__global__ void __launch_bounds__(256) ka_kernel(const float* __restrict__ X, int E) {
    __shared__ float w[8][128];
    __shared__ float bks[8];
    for (int i = threadIdx.x; i < 1024; i += 256) w[i >> 7][i & 127] = g_wkAT[i];
    if (threadIdx.x < 8) bks[threadIdx.x] = g_bkA[threadIdx.x];
    __syncthreads();
    int warp = (int)((blockIdx.x * 256 + threadIdx.x) >> 5);
    int lane = threadIdx.x & 31;
    if (warp >= E) return;
    float4 x = ((const float4*)(X + (size_t)warp * 128))[lane];
    #pragma unroll
    for (int h = 0; h < 8; h++) {
        float4 wv = *(const float4*)&w[h][lane * 4];
        float s = x.x * wv.x + x.y * wv.y + x.z * wv.z + x.w * wv.w;
        #pragma unroll
        for (int off = 16; off; off >>= 1) s += __shfl_xor_sync(0xffffffffu, s, off);
        if (lane == h) g_kA[warp * 8 + h] = s + bks[h];
    }
}

// -------- K3: zero output + init max/denom ----
__global__ void init_kernel(float* __restrict__ out, int E) {
    int i = blockIdx.x * blockDim.x + threadIdx.x;
    if (i < E * 128) out[i] = 0.f;
    if (i < E * 8) { g_maxk[i] = 0u; g_denom[i] = 0.f; }
}

// -------- K4: segment max of kA[src] grouped by dst ----
__global__ void segmax_kernel(const void* __restrict__ idx, int Mp) {
    int i = blockIdx.x * blockDim.x + threadIdx.x;
    if (i >= Mp * 8) return;
    int m = i >> 3, h = i & 7;
    int is64 = g_idx64;
    int s = ld_idx(idx, m, is64);
    int d = ld_idx(idx, (long long)Mp + m, is64);
    atomicMax(&g_maxk[d * 8 + h], enc_f(g_kA[s * 8 + h]));
}

// -------- K5: softmax denominators ----
__global__ void denom_kernel(const void* __restrict__ idx, int Mp) {
    int i = blockIdx.x * blockDim.x + threadIdx.x;
    if (i >= Mp * 8) return;
    int m = i >> 3, h = i & 7;
    int is64 = g_idx64;
    int s = ld_idx(idx, m, is64);
    int d = ld_idx(idx, (long long)Mp + m, is64);
    float w = __expf(g_kA[s * 8 + h] - dec_f(g_maxk[d * 8 + h]));
    atomicAdd(&g_denom[d * 8 + h], w);
}

// -------- K6: out[dst] += attn * Vh[src]  (warp per pair, vector reductions) ----
__global__ void __launch_bounds__(256) agg_kernel(const void* __restrict__ idx,
                                                  float* __restrict__ out, int Mp) {
    int g = blockIdx.x * blockDim.x + threadIdx.x;
    int m = g >> 5;
    if (m >= Mp) return;
    int lane = threadIdx.x & 31;
    int is64 = g_idx64;
    int s = ld_idx(idx, m, is64);
    int d = ld_idx(idx, (long long)Mp + m, is64);
    int h = lane >> 2;
    float ka  = g_kA[s * 8 + h];
    float mx  = dec_f(g_maxk[d * 8 + h]);
    float den = g_denom[d * 8 + h];
    float attn = __expf(ka - mx) / (den + 1e-16f);
    float4 v = ((const float4*)(g_Vh + (size_t)s * 128))[lane];
    float* addr = out + (size_t)d * 128 + lane * 4;
    asm volatile("red.global.add.v4.f32 [%0], {%1, %2, %3, %4};"
                 :: "l"(addr), "f"(v.x * attn), "f"(v.y * attn),
                    "f"(v.z * attn), "f"(v.w * attn)
                 : "memory");
}

extern "C" void kernel_launch(void* const* d_in, const int* in_sizes, int n_in,
                              void* d_out, int out_size) {
    const float* edge_attr = (const float*)d_in[0];
    const void*  idx       = d_in[1];
    // d_in[2]=Wq, d_in[3]=bq are algebraically dead (softmax shift cancels Q)
    const float* Wk = (const float*)d_in[4];
    const float* bk = (const float*)d_in[5];
    const float* Wv = (const float*)d_in[6];
    const float* bv = (const float*)d_in[7];
    const float* Aw = (const float*)d_in[8];
    float* out = (float*)d_out;

    int E = in_sizes[0] / 128;
    int M = in_sizes[1] / 2;
    if (E > E_CAP) E = E_CAP;
    if (M > M_CAP) M = M_CAP;

    prep_kernel<<<1, 128>>>(Wk, bk, Aw);
    detect_kernel<<<1, 32>>>(idx, E);

    dim3 ggrid(2, (E + 63) / 64);
    gemm_vh_kernel<<<ggrid, 256>>>(edge_attr, Wv, bv, E);

    ka_kernel<<<(E * 32 + 255) / 256, 256>>>(edge_attr, E);
    init_kernel<<<(E * 128 + 255) / 256, 256>>>(out, E);
    segmax_kernel<<<(M * 8 + 255) / 256, 256>>>(idx, M);
    denom_kernel<<<(M * 8 + 255) / 256, 256>>>(idx, M);
    agg_kernel<<<(int)(((long long)M * 32 + 255) / 256), 256>>>(idx, out, M);
}

// round 2
// speedup vs baseline: 1.5393x; 1.5393x over previous
#include <cuda_runtime.h>
#include <cstdint>

#define E_CAP 100000
#define M_CAP 1000000

// -------- device scratch --------
__device__ float    g_Vh[(size_t)E_CAP * 128];   // V projection [E,128]
__device__ float    g_expk[E_CAP * 8];           // exp(kA) per edge/head
__device__ float    g_denom[E_CAP * 8];          // softmax denominators
__device__ float    g_wkAT[8 * 128];             // pre-contracted Wk·Aw, [h][k]
__device__ float    g_bkA[8];
__device__ int      g_src[M_CAP];
__device__ int      g_dst[M_CAP];
__device__ int      g_idx64;

__device__ __forceinline__ int ld_idx(const void* idx, long long pos, int is64) {
    return is64 ? (int)((const long long*)idx)[pos] : ((const int*)idx)[pos];
}

// -------- K0: pre-contract Wk with Aw (Q is algebraically dead; max-shift dropped) --
__global__ void prep_kernel(const float* __restrict__ Wk, const float* __restrict__ bk,
                            const float* __restrict__ Aw) {
    int k = threadIdx.x;
    if (k < 128) {
        #pragma unroll
        for (int h = 0; h < 8; h++) {
            float s = 0.f;
            #pragma unroll
            for (int d = 0; d < 16; d++) s += Wk[k * 128 + h * 16 + d] * Aw[d * 8 + h];
            g_wkAT[h * 128 + k] = s;
        }
    }
    if (k < 8) {
        float s = 0.f;
        #pragma unroll
        for (int d = 0; d < 16; d++) s += bk[k * 16 + d] * Aw[d * 8 + k];
        g_bkA[k] = s;
    }
}

__global__ void detect_kernel(const void* __restrict__ idx, int E) {
    if (threadIdx.x == 0) {
        const long long* p = (const long long*)idx;
        int ok = 1;
        for (int i = 0; i < 64; i++) {
            long long v = p[i];
            if (v < 0 || v >= (long long)E) { ok = 0; break; }
        }
        g_idx64 = ok;
    }
}

// -------- K1: Vh = edge_attr @ Wv + bv via tf32 mma.sync (m16n8k8) --------
// Block: 256 thr = 8 warps. Block tile 128(M)x128(N). Warp tile 32x64.
__global__ void __launch_bounds__(256) gemm_vh_tf32_kernel(
    const float* __restrict__ A, const float* __restrict__ B,
    const float* __restrict__ bias, int E)
{
    __shared__ unsigned As[128][36];  // [row][k] tf32 bits, padded
    __shared__ unsigned Bs[32][132];  // [k][n]   tf32 bits, padded

    const int t = threadIdx.x;
    const int warp = t >> 5, lane = t & 31;
    const int gid = lane >> 2, tid4 = lane & 3;
    const int wm = warp & 3, wn = warp >> 2;
    const int row0 = blockIdx.x * 128;

    float c[2][8][4];
    #pragma unroll
    for (int i = 0; i < 2; i++)
        #pragma unroll
        for (int j = 0; j < 8; j++)
            #pragma unroll
            for (int r = 0; r < 4; r++) c[i][j][r] = 0.f;

    const int a_kq = t & 7;        // float4 col within 32-k chunk
    const int a_r0 = t >> 3;       // 0..31
    const int b_n4 = (t & 31) * 4;
    const int b_k0 = t >> 5;       // 0..7

    for (int k0 = 0; k0 < 128; k0 += 32) {
        // load A chunk 128x32 (clamp rows; stores guarded later)
        #pragma unroll
        for (int p = 0; p < 4; p++) {
            int row = a_r0 + p * 32;
            int grow = row0 + row; if (grow >= E) grow = E - 1;
            float4 v = *(const float4*)(A + (size_t)grow * 128 + k0 + a_kq * 4);
            unsigned u0, u1, u2, u3;
            asm("cvt.rna.tf32.f32 %0, %1;" : "=r"(u0) : "f"(v.x));
            asm("cvt.rna.tf32.f32 %0, %1;" : "=r"(u1) : "f"(v.y));
            asm("cvt.rna.tf32.f32 %0, %1;" : "=r"(u2) : "f"(v.z));
            asm("cvt.rna.tf32.f32 %0, %1;" : "=r"(u3) : "f"(v.w));
            As[row][a_kq * 4 + 0] = u0; As[row][a_kq * 4 + 1] = u1;
            As[row][a_kq * 4 + 2] = u2; As[row][a_kq * 4 + 3] = u3;
        }
        // load B chunk 32x128
        #pragma unroll
        for (int p = 0; p < 4; p++) {
            int kk = b_k0 + p * 8;
            float4 v = *(const float4*)(B + (size_t)(k0 + kk) * 128 + b_n4);
            unsigned u0, u1, u2, u3;
            asm("cvt.rna.tf32.f32 %0, %1;" : "=r"(u0) : "f"(v.x));
            asm("cvt.rna.tf32.f32 %0, %1;" : "=r"(u1) : "f"(v.y));
            asm("cvt.rna.tf32.f32 %0, %1;" : "=r"(u2) : "f"(v.z));
            asm("cvt.rna.tf32.f32 %0, %1;" : "=r"(u3) : "f"(v.w));
            Bs[kk][b_n4 + 0] = u0; Bs[kk][b_n4 + 1] = u1;
            Bs[kk][b_n4 + 2] = u2; Bs[kk][b_n4 + 3] = u3;
        }
        __syncthreads();

        #pragma unroll
        for (int ks = 0; ks < 4; ks++) {
            int kb = ks * 8;
            unsigned af[2][4];
            #pragma unroll
            for (int ma = 0; ma < 2; ma++) {
                int ar = wm * 32 + ma * 16;
                af[ma][0] = As[ar + gid    ][kb + tid4];
                af[ma][1] = As[ar + gid + 8][kb + tid4];
                af[ma][2] = As[ar + gid    ][kb + tid4 + 4];
                af[ma][3] = As[ar + gid + 8][kb + tid4 + 4];
            }
            #pragma unroll
            for (int na = 0; na < 8; na++) {
                int bc = wn * 64 + na * 8 + gid;
                unsigned b0 = Bs[kb + tid4    ][bc];
                unsigned b1 = Bs[kb + tid4 + 4][bc];
                #pragma unroll
                for (int ma = 0; ma < 2; ma++) {
                    asm volatile(
                        "mma.sync.aligned.m16n8k8.row.col.f32.tf32.tf32.f32 "
                        "{%0,%1,%2,%3}, {%4,%5,%6,%7}, {%8,%9}, {%0,%1,%2,%3};"
                        : "+f"(c[ma][na][0]), "+f"(c[ma][na][1]),
                          "+f"(c[ma][na][2]), "+f"(c[ma][na][3])
                        : "r"(af[ma][0]), "r"(af[ma][1]), "r"(af[ma][2]), "r"(af[ma][3]),
                          "r"(b0), "r"(b1));
                }
            }
        }
        __syncthreads();
    }

    // epilogue: bias + store
    #pragma unroll
    for (int ma = 0; ma < 2; ma++) {
        int r_base = row0 + wm * 32 + ma * 16 + gid;
        #pragma unroll
        for (int na = 0; na < 8; na++) {
            int col = wn * 64 + na * 8 + 2 * tid4;
            float b0 = bias[col], b1 = bias[col + 1];
            if (r_base < E) {
                g_Vh[(size_t)r_base * 128 + col    ] = c[ma][na][0] + b0;
                g_Vh[(size_t)r_base * 128 + col + 1] = c[ma][na][1] + b1;
            }
            if (r_base + 8 < E) {
                g_Vh[(size_t)(r_base + 8) * 128 + col    ] = c[ma][na][2] + b0;
                g_Vh[(size_t)(r_base + 8) * 128 + col + 1] = c[ma][na][3] + b1;
            }
        }
    }
}

// -------- K2: expk[e,h] = exp(edge_attr[e]·wkA[h] + bkA[h]); 8 lanes per row ----
__global__ void __launch_bounds__(256) ka_kernel(const float* __restrict__ X, int E) {
    __shared__ float wt[8][132];   // [j][h*16+c] lane-major weight copy
    __shared__ float bks[8];
    for (int i = threadIdx.x; i < 1024; i += 256) {
        int j = i >> 7, rem = i & 127, h = rem >> 4, cc = rem & 15;
        wt[j][h * 16 + cc] = g_wkAT[h * 128 + j * 16 + cc];
    }
    if (threadIdx.x < 8) bks[threadIdx.x] = g_bkA[threadIdx.x];
    __syncthreads();

    int warp = threadIdx.x >> 5, lane = threadIdx.x & 31;
    int g = lane >> 3, j = lane & 7;
    int row = blockIdx.x * 32 + warp * 4 + g;
    if (row >= E) return;

    const float4* xp = (const float4*)(X + (size_t)row * 128 + j * 16);
    float4 x0 = xp[0], x1 = xp[1], x2 = xp[2], x3 = xp[3];

    float acc[8];
    #pragma unroll
    for (int h = 0; h < 8; h++) {
        const float4* wp = (const float4*)&wt[j][h * 16];
        float4 w0 = wp[0], w1 = wp[1], w2 = wp[2], w3 = wp[3];
        float s = x0.x * w0.x + x0.y * w0.y + x0.z * w0.z + x0.w * w0.w;
        s += x1.x * w1.x + x1.y * w1.y + x1.z * w1.z + x1.w * w1.w;
        s += x2.x * w2.x + x2.y * w2.y + x2.z * w2.z + x2.w * w2.w;
        s += x3.x * w3.x + x3.y * w3.y + x3.z * w3.z + x3.w * w3.w;
        acc[h] = s;
    }
    #pragma unroll
    for (int off = 4; off; off >>= 1)
        #pragma unroll
        for (int h = 0; h < 8; h++)
            acc[h] += __shfl_xor_sync(0xffffffffu, acc[h], off);
    // every lane in the 8-lane group now has all 8 head sums; lane j writes head j
    g_expk[row * 8 + j] = __expf(acc[j] + bks[j]);
}

// -------- K3: zero output + denom ----
__global__ void init_kernel(float* __restrict__ out, int E) {
    int i = blockIdx.x * blockDim.x + threadIdx.x;
    if (i < E * 128) out[i] = 0.f;
    if (i < E * 8) g_denom[i] = 0.f;
}

// -------- K4: convert indices + accumulate denominators (vector reds) ----
__global__ void __launch_bounds__(256) convdenom_kernel(const void* __restrict__ idx, int Mp) {
    int m = blockIdx.x * blockDim.x + threadIdx.x;
    if (m >= Mp) return;
    int is64 = g_idx64;
    int s = ld_idx(idx, m, is64);
    int d = ld_idx(idx, (long long)Mp + m, is64);
    g_src[m] = s; g_dst[m] = d;
    float4 e0 = *(const float4*)(g_expk + s * 8);
    float4 e1 = *(const float4*)(g_expk + s * 8 + 4);
    float* a0 = g_denom + d * 8;
    asm volatile("red.global.add.v4.f32 [%0], {%1, %2, %3, %4};"
                 :: "l"(a0), "f"(e0.x), "f"(e0.y), "f"(e0.z), "f"(e0.w) : "memory");
    asm volatile("red.global.add.v4.f32 [%0], {%1, %2, %3, %4};"
                 :: "l"(a0 + 4), "f"(e1.x), "f"(e1.y), "f"(e1.z), "f"(e1.w) : "memory");
}

// -------- K5: out[dst] += (expk[src]/denom[dst]) * Vh[src]  (warp per pair) ----
__global__ void __launch_bounds__(256) agg_kernel(float* __restrict__ out, int Mp) {
    int m = (blockIdx.x * blockDim.x + threadIdx.x) >> 5;
    if (m >= Mp) return;
    int lane = threadIdx.x & 31;
    int s = g_src[m];
    int d = g_dst[m];
    int h = lane >> 2;
    float attn = __fdividef(g_expk[s * 8 + h], g_denom[d * 8 + h]);
    float4 v = ((const float4*)(g_Vh + (size_t)s * 128))[lane];
    float* addr = out + (size_t)d * 128 + lane * 4;
    asm volatile("red.global.add.v4.f32 [%0], {%1, %2, %3, %4};"
                 :: "l"(addr), "f"(v.x * attn), "f"(v.y * attn),
                    "f"(v.z * attn), "f"(v.w * attn) : "memory");
}

extern "C" void kernel_launch(void* const* d_in, const int* in_sizes, int n_in,
                              void* d_out, int out_size) {
    const float* edge_attr = (const float*)d_in[0];
    const void*  idx       = d_in[1];
    // d_in[2]=Wq, d_in[3]=bq dead (softmax shift cancels Q)
    const float* Wk = (const float*)d_in[4];
    const float* bk = (const float*)d_in[5];
    const float* Wv = (const float*)d_in[6];
    const float* bv = (const float*)d_in[7];
    const float* Aw = (const float*)d_in[8];
    float* out = (float*)d_out;

    int E = in_sizes[0] / 128;
    int M = in_sizes[1] / 2;
    if (E > E_CAP) E = E_CAP;
    if (M > M_CAP) M = M_CAP;

    prep_kernel<<<1, 128>>>(Wk, bk, Aw);
    detect_kernel<<<1, 32>>>(idx, E);
    init_kernel<<<(E * 128 + 255) / 256, 256>>>(out, E);
    gemm_vh_tf32_kernel<<<(E + 127) / 128, 256>>>(edge_attr, Wv, bv, E);
    ka_kernel<<<(E + 31) / 32, 256>>>(edge_attr, E);
    convdenom_kernel<<<(M + 255) / 256, 256>>>(idx, M);
    agg_kernel<<<(int)(((long long)M * 32 + 255) / 256), 256>>>(out, M);
}

// round 7
// speedup vs baseline: 2.4925x; 1.6192x over previous
#include <cuda_runtime.h>
#include <cstdint>

#define E_CAP 100000
#define M_CAP 1000000

// -------- device scratch --------
__device__ float    g_Vh[(size_t)E_CAP * 128];   // V projection [E,128]
__device__ float    g_expk[E_CAP * 8];           // exp(kA) per edge/head
__device__ float    g_wkAT[8 * 128];             // pre-contracted Wk·Aw, [h][k]
__device__ float    g_bkA[8];
__device__ int      g_cnt[E_CAP];                // per-dst pair counts
__device__ int      g_rowptr[E_CAP + 1];         // CSR row pointers
__device__ int      g_head[E_CAP];               // scatter cursors
__device__ int      g_ssort[M_CAP];              // src ids sorted by dst
__device__ int      g_part[128];                 // scan partials
__device__ int      g_idx64;

__device__ __forceinline__ int ld_idx(const void* idx, long long pos, int is64) {
    return is64 ? (int)((const long long*)idx)[pos] : ((const int*)idx)[pos];
}

// -------- K0: pre-contract Wk with Aw (Q is algebraically dead; softmax shift cancels) --
__global__ void prep_kernel(const float* __restrict__ Wk, const float* __restrict__ bk,
                            const float* __restrict__ Aw) {
    int k = threadIdx.x;
    if (k < 128) {
        #pragma unroll
        for (int h = 0; h < 8; h++) {
            float s = 0.f;
            #pragma unroll
            for (int d = 0; d < 16; d++) s += Wk[k * 128 + h * 16 + d] * Aw[d * 8 + h];
            g_wkAT[h * 128 + k] = s;
        }
    }
    if (k < 8) {
        float s = 0.f;
        #pragma unroll
        for (int d = 0; d < 16; d++) s += bk[k * 16 + d] * Aw[d * 8 + k];
        g_bkA[k] = s;
    }
}

__global__ void detect_kernel(const void* __restrict__ idx, int E) {
    if (threadIdx.x == 0) {
        const long long* p = (const long long*)idx;
        int ok = 1;
        for (int i = 0; i < 64; i++) {
            long long v = p[i];
            if (v < 0 || v >= (long long)E) { ok = 0; break; }
        }
        g_idx64 = ok;
    }
}

// -------- K1: Vh = edge_attr @ Wv + bv via tf32 mma.sync (m16n8k8) --------
__global__ void __launch_bounds__(256) gemm_vh_tf32_kernel(
    const float* __restrict__ A, const float* __restrict__ B,
    const float* __restrict__ bias, int E)
{
    __shared__ unsigned As[128][36];
    __shared__ unsigned Bs[32][132];

    const int t = threadIdx.x;
    const int warp = t >> 5, lane = t & 31;
    const int gid = lane >> 2, tid4 = lane & 3;
    const int wm = warp & 3, wn = warp >> 2;
    const int row0 = blockIdx.x * 128;

    float c[2][8][4];
    #pragma unroll
    for (int i = 0; i < 2; i++)
        #pragma unroll
        for (int j = 0; j < 8; j++)
            #pragma unroll
            for (int r = 0; r < 4; r++) c[i][j][r] = 0.f;

    const int a_kq = t & 7;
    const int a_r0 = t >> 3;
    const int b_n4 = (t & 31) * 4;
    const int b_k0 = t >> 5;

    for (int k0 = 0; k0 < 128; k0 += 32) {
        #pragma unroll
        for (int p = 0; p < 4; p++) {
            int row = a_r0 + p * 32;
            int grow = row0 + row; if (grow >= E) grow = E - 1;
            float4 v = *(const float4*)(A + (size_t)grow * 128 + k0 + a_kq * 4);
            unsigned u0, u1, u2, u3;
            asm("cvt.rna.tf32.f32 %0, %1;" : "=r"(u0) : "f"(v.x));
            asm("cvt.rna.tf32.f32 %0, %1;" : "=r"(u1) : "f"(v.y));
            asm("cvt.rna.tf32.f32 %0, %1;" : "=r"(u2) : "f"(v.z));
            asm("cvt.rna.tf32.f32 %0, %1;" : "=r"(u3) : "f"(v.w));
            As[row][a_kq * 4 + 0] = u0; As[row][a_kq * 4 + 1] = u1;
            As[row][a_kq * 4 + 2] = u2; As[row][a_kq * 4 + 3] = u3;
        }
        #pragma unroll
        for (int p = 0; p < 4; p++) {
            int kk = b_k0 + p * 8;
            float4 v = *(const float4*)(B + (size_t)(k0 + kk) * 128 + b_n4);
            unsigned u0, u1, u2, u3;
            asm("cvt.rna.tf32.f32 %0, %1;" : "=r"(u0) : "f"(v.x));
            asm("cvt.rna.tf32.f32 %0, %1;" : "=r"(u1) : "f"(v.y));
            asm("cvt.rna.tf32.f32 %0, %1;" : "=r"(u2) : "f"(v.z));
            asm("cvt.rna.tf32.f32 %0, %1;" : "=r"(u3) : "f"(v.w));
            Bs[kk][b_n4 + 0] = u0; Bs[kk][b_n4 + 1] = u1;
            Bs[kk][b_n4 + 2] = u2; Bs[kk][b_n4 + 3] = u3;
        }
        __syncthreads();

        #pragma unroll
        for (int ks = 0; ks < 4; ks++) {
            int kb = ks * 8;
            unsigned af[2][4];
            #pragma unroll
            for (int ma = 0; ma < 2; ma++) {
                int ar = wm * 32 + ma * 16;
                af[ma][0] = As[ar + gid    ][kb + tid4];
                af[ma][1] = As[ar + gid + 8][kb + tid4];
                af[ma][2] = As[ar + gid    ][kb + tid4 + 4];
                af[ma][3] = As[ar + gid + 8][kb + tid4 + 4];
            }
            #pragma unroll
            for (int na = 0; na < 8; na++) {
                int bc = wn * 64 + na * 8 + gid;
                unsigned b0 = Bs[kb + tid4    ][bc];
                unsigned b1 = Bs[kb + tid4 + 4][bc];
                #pragma unroll
                for (int ma = 0; ma < 2; ma++) {
                    asm volatile(
                        "mma.sync.aligned.m16n8k8.row.col.f32.tf32.tf32.f32 "
                        "{%0,%1,%2,%3}, {%4,%5,%6,%7}, {%8,%9}, {%0,%1,%2,%3};"
                        : "+f"(c[ma][na][0]), "+f"(c[ma][na][1]),
                          "+f"(c[ma][na][2]), "+f"(c[ma][na][3])
                        : "r"(af[ma][0]), "r"(af[ma][1]), "r"(af[ma][2]), "r"(af[ma][3]),
                          "r"(b0), "r"(b1));
                }
            }
        }
        __syncthreads();
    }

    #pragma unroll
    for (int ma = 0; ma < 2; ma++) {
        int r_base = row0 + wm * 32 + ma * 16 + gid;
        #pragma unroll
        for (int na = 0; na < 8; na++) {
            int col = wn * 64 + na * 8 + 2 * tid4;
            float b0 = bias[col], b1 = bias[col + 1];
            if (r_base < E) {
                g_Vh[(size_t)r_base * 128 + col    ] = c[ma][na][0] + b0;
                g_Vh[(size_t)r_base * 128 + col + 1] = c[ma][na][1] + b1;
            }
            if (r_base + 8 < E) {
                g_Vh[(size_t)(r_base + 8) * 128 + col    ] = c[ma][na][2] + b0;
                g_Vh[(size_t)(r_base + 8) * 128 + col + 1] = c[ma][na][3] + b1;
            }
        }
    }
}

// -------- K2: expk[e,h] = exp(edge_attr[e]·wkA[h] + bkA[h]); 8 lanes per row ----
__global__ void __launch_bounds__(256) ka_kernel(const float* __restrict__ X, int E) {
    __shared__ float wt[8][132];
    __shared__ float bks[8];
    for (int i = threadIdx.x; i < 1024; i += 256) {
        int j = i >> 7, rem = i & 127, h = rem >> 4, cc = rem & 15;
        wt[j][h * 16 + cc] = g_wkAT[h * 128 + j * 16 + cc];
    }
    if (threadIdx.x < 8) bks[threadIdx.x] = g_bkA[threadIdx.x];
    __syncthreads();

    int warp = threadIdx.x >> 5, lane = threadIdx.x & 31;
    int g = lane >> 3, j = lane & 7;
    int row = blockIdx.x * 32 + warp * 4 + g;
    if (row >= E) return;

    const float4* xp = (const float4*)(X + (size_t)row * 128 + j * 16);
    float4 x0 = xp[0], x1 = xp[1], x2 = xp[2], x3 = xp[3];

    float acc[8];
    #pragma unroll
    for (int h = 0; h < 8; h++) {
        const float4* wp = (const float4*)&wt[j][h * 16];
        float4 w0 = wp[0], w1 = wp[1], w2 = wp[2], w3 = wp[3];
        float s = x0.x * w0.x + x0.y * w0.y + x0.z * w0.z + x0.w * w0.w;
        s += x1.x * w1.x + x1.y * w1.y + x1.z * w1.z + x1.w * w1.w;
        s += x2.x * w2.x + x2.y * w2.y + x2.z * w2.z + x2.w * w2.w;
        s += x3.x * w3.x + x3.y * w3.y + x3.z * w3.z + x3.w * w3.w;
        acc[h] = s;
    }
    #pragma unroll
    for (int off = 4; off; off >>= 1)
        #pragma unroll
        for (int h = 0; h < 8; h++)
            acc[h] += __shfl_xor_sync(0xffffffffu, acc[h], off);
    g_expk[row * 8 + j] = __expf(acc[j] + bks[j]);
}

// -------- CSR build --------
__global__ void zerocnt_kernel(int E) {
    int i = blockIdx.x * blockDim.x + threadIdx.x;
    if (i < E) g_cnt[i] = 0;
}

__global__ void hist_kernel(const void* __restrict__ idx, int Mp) {
    int m = blockIdx.x * blockDim.x + threadIdx.x;
    if (m >= Mp) return;
    int d = ld_idx(idx, (long long)Mp + m, g_idx64);
    atomicAdd(&g_cnt[d], 1);
}

__global__ void __launch_bounds__(1024) scan1_kernel(int E) {
    int i = blockIdx.x * 1024 + threadIdx.x;
    int c = (i < E) ? g_cnt[i] : 0;
    int lane = threadIdx.x & 31, w = threadIdx.x >> 5;
    int v = c;
    #pragma unroll
    for (int o = 1; o < 32; o <<= 1) {
        int t = __shfl_up_sync(0xffffffffu, v, o);
        if (lane >= o) v += t;
    }
    __shared__ int ws[32];
    if (lane == 31) ws[w] = v;
    __syncthreads();
    if (w == 0) {
        int t = ws[lane];
        #pragma unroll
        for (int o = 1; o < 32; o <<= 1) {
            int u = __shfl_up_sync(0xffffffffu, t, o);
            if (lane >= o) t += u;
        }
        ws[lane] = t;
    }
    __syncthreads();
    int off = (w > 0) ? ws[w - 1] : 0;
    int incl = v + off;
    if (i < E) g_rowptr[i] = incl - c;   // block-local exclusive
    if (threadIdx.x == 1023) g_part[blockIdx.x] = incl;
}

__global__ void scan2_kernel(int NB, int Mp, int E) {
    __shared__ int sh[128];
    int t = threadIdx.x;
    int v = (t < NB) ? g_part[t] : 0;
    sh[t] = v;
    __syncthreads();
    #pragma unroll
    for (int o = 1; o < 128; o <<= 1) {
        int u = (t >= o) ? sh[t - o] : 0;
        __syncthreads();
        sh[t] += u;
        __syncthreads();
    }
    if (t < NB) g_part[t] = sh[t] - v;   // exclusive block offsets
    if (t == 0) g_rowptr[E] = Mp;
}

__global__ void scan3_kernel(int E) {
    int i = blockIdx.x * blockDim.x + threadIdx.x;
    if (i >= E) return;
    int r = g_rowptr[i] + g_part[i >> 10];
    g_rowptr[i] = r;
    g_head[i] = r;
}

__global__ void scatter_kernel(const void* __restrict__ idx, int Mp) {
    int m = blockIdx.x * blockDim.x + threadIdx.x;
    if (m >= Mp) return;
    int is64 = g_idx64;
    int s = ld_idx(idx, m, is64);
    int d = ld_idx(idx, (long long)Mp + m, is64);
    int pos = atomicAdd(&g_head[d], 1);
    g_ssort[pos] = s;
}

// -------- K6: gather-only aggregation, warp per destination edge ----
// out[d,h,:] = (sum_s expk[s,h]*Vh[s,h,:]) / (sum_s expk[s,h] + 1e-16)
__global__ void __launch_bounds__(256) agg_csr_kernel(float* __restrict__ out, int E) {
    int d = (blockIdx.x * 256 + threadIdx.x) >> 5;
    if (d >= E) return;
    int lane = threadIdx.x & 31;
    int h = lane >> 2;
    int beg = g_rowptr[d], end = g_rowptr[d + 1];

    float ax = 0.f, ay = 0.f, az = 0.f, aw = 0.f, sumw = 0.f;
    int s = (beg < end) ? g_ssort[beg] : 0;
    for (int p = beg; p < end; p++) {
        int s_next = (p + 1 < end) ? g_ssort[p + 1] : 0;
        float w = g_expk[s * 8 + h];
        float4 v = *(const float4*)(g_Vh + (size_t)s * 128 + lane * 4);
        ax += w * v.x; ay += w * v.y; az += w * v.z; aw += w * v.w;
        sumw += w;
        s = s_next;
    }
    float inv = __fdividef(1.f, sumw + 1e-16f);
    float4 o = make_float4(ax * inv, ay * inv, az * inv, aw * inv);
    *(float4*)(out + (size_t)d * 128 + lane * 4) = o;
}

extern "C" void kernel_launch(void* const* d_in, const int* in_sizes, int n_in,
                              void* d_out, int out_size) {
    const float* edge_attr = (const float*)d_in[0];
    const void*  idx       = d_in[1];
    // d_in[2]=Wq, d_in[3]=bq dead (softmax shift cancels Q)
    const float* Wk = (const float*)d_in[4];
    const float* bk = (const float*)d_in[5];
    const float* Wv = (const float*)d_in[6];
    const float* bv = (const float*)d_in[7];
    const float* Aw = (const float*)d_in[8];
    float* out = (float*)d_out;

    int E = in_sizes[0] / 128;
    int M = in_sizes[1] / 2;
    if (E > E_CAP) E = E_CAP;
    if (M > M_CAP) M = M_CAP;
    int NB = (E + 1023) / 1024;

    prep_kernel<<<1, 128>>>(Wk, bk, Aw);
    detect_kernel<<<1, 32>>>(idx, E);
    zerocnt_kernel<<<(E + 255) / 256, 256>>>(E);
    gemm_vh_tf32_kernel<<<(E + 127) / 128, 256>>>(edge_attr, Wv, bv, E);
    ka_kernel<<<(E + 31) / 32, 256>>>(edge_attr, E);
    hist_kernel<<<(M + 255) / 256, 256>>>(idx, M);
    scan1_kernel<<<NB, 1024>>>(E);
    scan2_kernel<<<1, 128>>>(NB, M, E);
    scan3_kernel<<<(E + 255) / 256, 256>>>(E);
    scatter_kernel<<<(M + 255) / 256, 256>>>(idx, M);
    agg_csr_kernel<<<(int)(((long long)E * 32 + 255) / 256), 256>>>(out, E);
}

// round 8
// speedup vs baseline: 3.2980x; 1.3232x over previous
#include <cuda_runtime.h>
#include <cstdint>

#define E_CAP 100000
#define M_CAP 1000000

// -------- device scratch --------
__device__ float    g_Vh[(size_t)E_CAP * 128];   // V projection [E,128]
__device__ float    g_expk[E_CAP * 8];           // exp(kA) per edge/head
__device__ float    g_wkAT[8 * 128];             // pre-contracted Wk·Aw, [h][k]
__device__ float    g_bkA[8];
__device__ int      g_cnt[E_CAP];                // per-dst pair counts
__device__ int      g_rowptr[E_CAP + 1];         // CSR row pointers
__device__ int      g_head[E_CAP];               // scatter cursors
__device__ int      g_ssort[M_CAP];              // src ids sorted by dst
__device__ int      g_part[128];                 // scan partials
__device__ int      g_idx64;

__device__ __forceinline__ int ld_idx(const void* idx, long long pos, int is64) {
    return is64 ? (int)((const long long*)idx)[pos] : ((const int*)idx)[pos];
}
__device__ __forceinline__ unsigned f2tf(float f) {
    unsigned u; asm("cvt.rna.tf32.f32 %0, %1;" : "=r"(u) : "f"(f)); return u;
}
__device__ __forceinline__ void cp16(void* smem_dst, const void* gptr) {
    unsigned saddr = (unsigned)__cvta_generic_to_shared(smem_dst);
    asm volatile("cp.async.cg.shared.global [%0], [%1], 16;" :: "r"(saddr), "l"(gptr));
}

// -------- K0: pre-contract Wk with Aw (Q is algebraically dead; softmax shift cancels) --
__global__ void prep_kernel(const float* __restrict__ Wk, const float* __restrict__ bk,
                            const float* __restrict__ Aw) {
    int k = threadIdx.x;
    if (k < 128) {
        #pragma unroll
        for (int h = 0; h < 8; h++) {
            float s = 0.f;
            #pragma unroll
            for (int d = 0; d < 16; d++) s += Wk[k * 128 + h * 16 + d] * Aw[d * 8 + h];
            g_wkAT[h * 128 + k] = s;
        }
    }
    if (k < 8) {
        float s = 0.f;
        #pragma unroll
        for (int d = 0; d < 16; d++) s += bk[k * 16 + d] * Aw[d * 8 + k];
        g_bkA[k] = s;
    }
}

__global__ void detect_kernel(const void* __restrict__ idx, int E) {
    if (threadIdx.x == 0) {
        const long long* p = (const long long*)idx;
        int ok = 1;
        for (int i = 0; i < 64; i++) {
            long long v = p[i];
            if (v < 0 || v >= (long long)E) { ok = 0; break; }
        }
        g_idx64 = ok;
    }
}

// -------- K1: Vh = edge_attr @ Wv + bv  AND  expk = exp(edge_attr·wkA + bkA) ----------
// tf32 mma.sync m16n8k8, cp.async double-buffered, kA fused as 8 extra N columns.
// Block 256 thr / 8 warps; tile M=128 N=128 Kchunk=32; warp tile 32x64.
// Dynamic smem layout (floats): As[2][128][36] | Bs[2][32][132] | Wks[8][132] | bks[8]
#define AS_OFF 0
#define BS_OFF (2 * 128 * 36)
#define WK_OFF (BS_OFF + 2 * 32 * 132)
#define BK_OFF (WK_OFF + 8 * 132)
#define SMEM_FLOATS (BK_OFF + 8)

__global__ void __launch_bounds__(256) gemm_vh_tf32_kernel(
    const float* __restrict__ A, const float* __restrict__ B,
    const float* __restrict__ bias, int E)
{
    extern __shared__ float sm[];
    float* As  = sm + AS_OFF;   // buf*4608 + row*36 + k
    float* Bs  = sm + BS_OFF;   // buf*4224 + k*132 + n
    float* Wks = sm + WK_OFF;   // h*132 + k  (full K=128)
    float* bks = sm + BK_OFF;

    const int t = threadIdx.x;
    const int warp = t >> 5, lane = t & 31;
    const int gid = lane >> 2, tid4 = lane & 3;
    const int wm = warp & 3, wn = warp >> 2;
    const int row0 = blockIdx.x * 128;

    // stage wkAT + bkA (plain stores; visible after first __syncthreads)
    for (int i = t; i < 1024; i += 256) Wks[(i >> 7) * 132 + (i & 127)] = g_wkAT[i];
    if (t < 8) bks[t] = g_bkA[t];

    float c[2][8][4];
    #pragma unroll
    for (int i = 0; i < 2; i++)
        #pragma unroll
        for (int j = 0; j < 8; j++)
            #pragma unroll
            for (int r = 0; r < 4; r++) c[i][j][r] = 0.f;
    float kc[2][4] = {};

    // cp.async indices: A chunk = 128x8 float4, B chunk = 32x32 float4
    const int a_row = t >> 3, a_c4 = t & 7;       // + p*32 rows
    const int b_k   = t >> 5, b_n4 = t & 31;      // + p*8 k-rows

    // prologue: prefetch chunk 0 into buf 0
    {
        #pragma unroll
        for (int p = 0; p < 4; p++) {
            int row = a_row + p * 32;
            int grow = row0 + row; if (grow >= E) grow = E - 1;
            cp16(&As[row * 36 + a_c4 * 4], A + (size_t)grow * 128 + a_c4 * 4);
        }
        #pragma unroll
        for (int p = 0; p < 4; p++) {
            int kk = b_k + p * 8;
            cp16(&Bs[kk * 132 + b_n4 * 4], B + (size_t)kk * 128 + b_n4 * 4);
        }
        asm volatile("cp.async.commit_group;");
    }

    #pragma unroll
    for (int i = 0; i < 4; i++) {
        const int k0 = i * 32;
        if (i < 3) {   // prefetch next chunk into other buffer
            const int kn = k0 + 32;
            float* Ad = As + ((i + 1) & 1) * 4608;
            float* Bd = Bs + ((i + 1) & 1) * 4224;
            #pragma unroll
            for (int p = 0; p < 4; p++) {
                int row = a_row + p * 32;
                int grow = row0 + row; if (grow >= E) grow = E - 1;
                cp16(&Ad[row * 36 + a_c4 * 4], A + (size_t)grow * 128 + kn + a_c4 * 4);
            }
            #pragma unroll
            for (int p = 0; p < 4; p++) {
                int kk = b_k + p * 8;
                cp16(&Bd[kk * 132 + b_n4 * 4], B + (size_t)(kn + kk) * 128 + b_n4 * 4);
            }
            asm volatile("cp.async.commit_group;");
            asm volatile("cp.async.wait_group 1;");
        } else {
            asm volatile("cp.async.wait_group 0;");
        }
        __syncthreads();

        const float* Ab = As + (i & 1) * 4608;
        const float* Bb = Bs + (i & 1) * 4224;

        #pragma unroll
        for (int ks = 0; ks < 4; ks++) {
            const int kb = ks * 8;
            unsigned af[2][4];
            #pragma unroll
            for (int ma = 0; ma < 2; ma++) {
                int ar = wm * 32 + ma * 16;
                af[ma][0] = f2tf(Ab[(ar + gid    ) * 36 + kb + tid4]);
                af[ma][1] = f2tf(Ab[(ar + gid + 8) * 36 + kb + tid4]);
                af[ma][2] = f2tf(Ab[(ar + gid    ) * 36 + kb + tid4 + 4]);
                af[ma][3] = f2tf(Ab[(ar + gid + 8) * 36 + kb + tid4 + 4]);
            }
            #pragma unroll
            for (int na = 0; na < 8; na++) {
                int bc = wn * 64 + na * 8 + gid;
                unsigned b0 = f2tf(Bb[(kb + tid4    ) * 132 + bc]);
                unsigned b1 = f2tf(Bb[(kb + tid4 + 4) * 132 + bc]);
                #pragma unroll
                for (int ma = 0; ma < 2; ma++) {
                    asm volatile(
                        "mma.sync.aligned.m16n8k8.row.col.f32.tf32.tf32.f32 "
                        "{%0,%1,%2,%3}, {%4,%5,%6,%7}, {%8,%9}, {%0,%1,%2,%3};"
                        : "+f"(c[ma][na][0]), "+f"(c[ma][na][1]),
                          "+f"(c[ma][na][2]), "+f"(c[ma][na][3])
                        : "r"(af[ma][0]), "r"(af[ma][1]), "r"(af[ma][2]), "r"(af[ma][3]),
                          "r"(b0), "r"(b1));
                }
            }
            if (wn == 0) {   // fused kA: B2[k][h] = wkAT[h][k]
                unsigned b0 = f2tf(Wks[gid * 132 + k0 + kb + tid4]);
                unsigned b1 = f2tf(Wks[gid * 132 + k0 + kb + tid4 + 4]);
                #pragma unroll
                for (int ma = 0; ma < 2; ma++) {
                    asm volatile(
                        "mma.sync.aligned.m16n8k8.row.col.f32.tf32.tf32.f32 "
                        "{%0,%1,%2,%3}, {%4,%5,%6,%7}, {%8,%9}, {%0,%1,%2,%3};"
                        : "+f"(kc[ma][0]), "+f"(kc[ma][1]),
                          "+f"(kc[ma][2]), "+f"(kc[ma][3])
                        : "r"(af[ma][0]), "r"(af[ma][1]), "r"(af[ma][2]), "r"(af[ma][3]),
                          "r"(b0), "r"(b1));
                }
            }
        }
        __syncthreads();
    }

    // epilogue: Vh = c + bias
    #pragma unroll
    for (int ma = 0; ma < 2; ma++) {
        int r_base = row0 + wm * 32 + ma * 16 + gid;
        #pragma unroll
        for (int na = 0; na < 8; na++) {
            int col = wn * 64 + na * 8 + 2 * tid4;
            float b0 = bias[col], b1 = bias[col + 1];
            if (r_base < E) {
                g_Vh[(size_t)r_base * 128 + col    ] = c[ma][na][0] + b0;
                g_Vh[(size_t)r_base * 128 + col + 1] = c[ma][na][1] + b1;
            }
            if (r_base + 8 < E) {
                g_Vh[(size_t)(r_base + 8) * 128 + col    ] = c[ma][na][2] + b0;
                g_Vh[(size_t)(r_base + 8) * 128 + col + 1] = c[ma][na][3] + b1;
            }
        }
    }
    // epilogue: expk = exp(kA + bkA) (wn==0 warps own all 128 rows x 8 heads)
    if (wn == 0) {
        int h0 = 2 * tid4;
        float bk0 = bks[h0], bk1 = bks[h0 + 1];
        #pragma unroll
        for (int ma = 0; ma < 2; ma++) {
            int r = row0 + wm * 32 + ma * 16 + gid;
            if (r < E) {
                g_expk[r * 8 + h0    ] = __expf(kc[ma][0] + bk0);
                g_expk[r * 8 + h0 + 1] = __expf(kc[ma][1] + bk1);
            }
            if (r + 8 < E) {
                g_expk[(r + 8) * 8 + h0    ] = __expf(kc[ma][2] + bk0);
                g_expk[(r + 8) * 8 + h0 + 1] = __expf(kc[ma][3] + bk1);
            }
        }
    }
}

// -------- CSR build --------
__global__ void zerocnt_kernel(int E) {
    int i = blockIdx.x * blockDim.x + threadIdx.x;
    if (i < E) g_cnt[i] = 0;
}

__global__ void hist_kernel(const void* __restrict__ idx, int Mp) {
    int m = blockIdx.x * blockDim.x + threadIdx.x;
    if (m >= Mp) return;
    int d = ld_idx(idx, (long long)Mp + m, g_idx64);
    atomicAdd(&g_cnt[d], 1);
}

__global__ void __launch_bounds__(1024) scan1_kernel(int E) {
    int i = blockIdx.x * 1024 + threadIdx.x;
    int c = (i < E) ? g_cnt[i] : 0;
    int lane = threadIdx.x & 31, w = threadIdx.x >> 5;
    int v = c;
    #pragma unroll
    for (int o = 1; o < 32; o <<= 1) {
        int t = __shfl_up_sync(0xffffffffu, v, o);
        if (lane >= o) v += t;
    }
    __shared__ int ws[32];
    if (lane == 31) ws[w] = v;
    __syncthreads();
    if (w == 0) {
        int t = ws[lane];
        #pragma unroll
        for (int o = 1; o < 32; o <<= 1) {
            int u = __shfl_up_sync(0xffffffffu, t, o);
            if (lane >= o) t += u;
        }
        ws[lane] = t;
    }
    __syncthreads();
    int off = (w > 0) ? ws[w - 1] : 0;
    int incl = v + off;
    if (i < E) g_rowptr[i] = incl - c;
    if (threadIdx.x == 1023) g_part[blockIdx.x] = incl;
}

__global__ void scan2_kernel(int NB, int Mp, int E) {
    __shared__ int sh[128];
    int t = threadIdx.x;
    int v = (t < NB) ? g_part[t] : 0;
    sh[t] = v;
    __syncthreads();
    #pragma unroll
    for (int o = 1; o < 128; o <<= 1) {
        int u = (t >= o) ? sh[t - o] : 0;
        __syncthreads();
        sh[t] += u;
        __syncthreads();
    }
    if (t < NB) g_part[t] = sh[t] - v;
    if (t == 0) g_rowptr[E] = Mp;
}

__global__ void scan3_kernel(int E) {
    int i = blockIdx.x * blockDim.x + threadIdx.x;
    if (i >= E) return;
    int r = g_rowptr[i] + g_part[i >> 10];
    g_rowptr[i] = r;
    g_head[i] = r;
}

__global__ void scatter_kernel(const void* __restrict__ idx, int Mp) {
    int m = blockIdx.x * blockDim.x + threadIdx.x;
    if (m >= Mp) return;
    int is64 = g_idx64;
    int s = ld_idx(idx, m, is64);
    int d = ld_idx(idx, (long long)Mp + m, is64);
    int pos = atomicAdd(&g_head[d], 1);
    g_ssort[pos] = s;
}

// -------- K6: gather-only aggregation, warp per destination edge ----
__global__ void __launch_bounds__(256) agg_csr_kernel(float* __restrict__ out, int E) {
    int d = (blockIdx.x * 256 + threadIdx.x) >> 5;
    if (d >= E) return;
    int lane = threadIdx.x & 31;
    int h = lane >> 2;
    int beg = g_rowptr[d], end = g_rowptr[d + 1];

    float ax = 0.f, ay = 0.f, az = 0.f, aw = 0.f, sumw = 0.f;
    int s = (beg < end) ? g_ssort[beg] : 0;
    for (int p = beg; p < end; p++) {
        int s_next = (p + 1 < end) ? g_ssort[p + 1] : 0;
        float w = g_expk[s * 8 + h];
        float4 v = *(const float4*)(g_Vh + (size_t)s * 128 + lane * 4);
        ax += w * v.x; ay += w * v.y; az += w * v.z; aw += w * v.w;
        sumw += w;
        s = s_next;
    }
    float inv = __fdividef(1.f, sumw + 1e-16f);
    float4 o = make_float4(ax * inv, ay * inv, az * inv, aw * inv);
    *(float4*)(out + (size_t)d * 128 + lane * 4) = o;
}

extern "C" void kernel_launch(void* const* d_in, const int* in_sizes, int n_in,
                              void* d_out, int out_size) {
    const float* edge_attr = (const float*)d_in[0];
    const void*  idx       = d_in[1];
    // d_in[2]=Wq, d_in[3]=bq dead (softmax shift cancels Q)
    const float* Wk = (const float*)d_in[4];
    const float* bk = (const float*)d_in[5];
    const float* Wv = (const float*)d_in[6];
    const float* bv = (const float*)d_in[7];
    const float* Aw = (const float*)d_in[8];
    float* out = (float*)d_out;

    int E = in_sizes[0] / 128;
    int M = in_sizes[1] / 2;
    if (E > E_CAP) E = E_CAP;
    if (M > M_CAP) M = M_CAP;
    int NB = (E + 1023) / 1024;

    // one-time host resources (streams/events are not device memory)
    static cudaStream_t s1 = nullptr;
    static cudaEvent_t evFork = nullptr, evJoin = nullptr;
    static bool smem_set = false;
    if (!s1) {
        cudaStreamCreateWithFlags(&s1, cudaStreamNonBlocking);
        cudaEventCreateWithFlags(&evFork, cudaEventDisableTiming);
        cudaEventCreateWithFlags(&evJoin, cudaEventDisableTiming);
    }
    if (!smem_set) {
        cudaFuncSetAttribute(gemm_vh_tf32_kernel,
                             cudaFuncAttributeMaxDynamicSharedMemorySize,
                             SMEM_FLOATS * sizeof(float));
        smem_set = true;
    }

    // stream 0: detect (needed by both chains), then fork
    detect_kernel<<<1, 32>>>(idx, E);
    cudaEventRecord(evFork, 0);
    cudaStreamWaitEvent(s1, evFork, 0);

    // chain A (stream 0): prep -> fused GEMM+kA
    prep_kernel<<<1, 128>>>(Wk, bk, Aw);
    gemm_vh_tf32_kernel<<<(E + 127) / 128, 256, SMEM_FLOATS * sizeof(float), 0>>>(
        edge_attr, Wv, bv, E);

    // chain B (stream s1): CSR build
    zerocnt_kernel<<<(E + 255) / 256, 256, 0, s1>>>(E);
    hist_kernel<<<(M + 255) / 256, 256, 0, s1>>>(idx, M);
    scan1_kernel<<<NB, 1024, 0, s1>>>(E);
    scan2_kernel<<<1, 128, 0, s1>>>(NB, M, E);
    scan3_kernel<<<(E + 255) / 256, 256, 0, s1>>>(E);
    scatter_kernel<<<(M + 255) / 256, 256, 0, s1>>>(idx, M);
    cudaEventRecord(evJoin, s1);

    // join, then aggregate on stream 0
    cudaStreamWaitEvent(0, evJoin, 0);
    agg_csr_kernel<<<(int)(((long long)E * 32 + 255) / 256), 256>>>(out, E);
}

// round 9
// speedup vs baseline: 3.8225x; 1.1590x over previous
#include <cuda_runtime.h>
#include <cuda_fp16.h>
#include <cstdint>

#define E_CAP 100000
#define M_CAP 1000000

// -------- device scratch --------
__device__ __half   g_Vh[(size_t)E_CAP * 128];   // V projection [E,128] fp16
__device__ float    g_expk[E_CAP * 8];           // exp(kA) per edge/head
__device__ float    g_wkAT[8 * 128];             // pre-contracted Wk·Aw, [h][k]
__device__ float    g_bkA[8];
__device__ int      g_cnt[E_CAP];                // per-dst pair counts
__device__ int      g_rowptr[E_CAP + 1];         // CSR row pointers
__device__ int      g_head[E_CAP];               // scatter cursors
__device__ int      g_ssort[M_CAP];              // src ids sorted by dst
__device__ int      g_part[128];                 // scan partials
__device__ int      g_idx64;

__device__ __forceinline__ int ld_idx(const void* idx, long long pos, int is64) {
    return is64 ? (int)((const long long*)idx)[pos] : ((const int*)idx)[pos];
}
__device__ __forceinline__ unsigned f2tf(float f) {
    unsigned u; asm("cvt.rna.tf32.f32 %0, %1;" : "=r"(u) : "f"(f)); return u;
}
__device__ __forceinline__ void cp16(void* smem_dst, const void* gptr) {
    unsigned saddr = (unsigned)__cvta_generic_to_shared(smem_dst);
    asm volatile("cp.async.cg.shared.global [%0], [%1], 16;" :: "r"(saddr), "l"(gptr));
}

// -------- K0: pre-contract Wk with Aw (Q is algebraically dead; softmax shift cancels) --
__global__ void prep_kernel(const float* __restrict__ Wk, const float* __restrict__ bk,
                            const float* __restrict__ Aw) {
    int k = threadIdx.x;
    if (k < 128) {
        #pragma unroll
        for (int h = 0; h < 8; h++) {
            float s = 0.f;
            #pragma unroll
            for (int d = 0; d < 16; d++) s += Wk[k * 128 + h * 16 + d] * Aw[d * 8 + h];
            g_wkAT[h * 128 + k] = s;
        }
    }
    if (k < 8) {
        float s = 0.f;
        #pragma unroll
        for (int d = 0; d < 16; d++) s += bk[k * 16 + d] * Aw[d * 8 + k];
        g_bkA[k] = s;
    }
}

// -------- merged: zero per-dst counters + detect index dtype ----
__global__ void init_detect_kernel(const void* __restrict__ idx, int E) {
    int i = blockIdx.x * blockDim.x + threadIdx.x;
    if (i < E) g_cnt[i] = 0;
    if (i == 0) {
        const long long* p = (const long long*)idx;
        int ok = 1;
        for (int q = 0; q < 64; q++) {
            long long v = p[q];
            if (v < 0 || v >= (long long)E) { ok = 0; break; }
        }
        g_idx64 = ok;
    }
}

// -------- K1: Vh(fp16) = edge_attr @ Wv + bv  AND  expk = exp(edge_attr·wkA + bkA) ----
// tf32 mma.sync m16n8k8, cp.async double-buffered, kA fused as 8 extra N columns.
#define AS_OFF 0
#define BS_OFF (2 * 128 * 36)
#define WK_OFF (BS_OFF + 2 * 32 * 132)
#define BK_OFF (WK_OFF + 8 * 132)
#define SMEM_FLOATS (BK_OFF + 8)

__global__ void __launch_bounds__(256) gemm_vh_tf32_kernel(
    const float* __restrict__ A, const float* __restrict__ B,
    const float* __restrict__ bias, int E)
{
    extern __shared__ float sm[];
    float* As  = sm + AS_OFF;   // buf*4608 + row*36 + k
    float* Bs  = sm + BS_OFF;   // buf*4224 + k*132 + n
    float* Wks = sm + WK_OFF;   // h*132 + k
    float* bks = sm + BK_OFF;

    const int t = threadIdx.x;
    const int warp = t >> 5, lane = t & 31;
    const int gid = lane >> 2, tid4 = lane & 3;
    const int wm = warp & 3, wn = warp >> 2;
    const int row0 = blockIdx.x * 128;

    for (int i = t; i < 1024; i += 256) Wks[(i >> 7) * 132 + (i & 127)] = g_wkAT[i];
    if (t < 8) bks[t] = g_bkA[t];

    float c[2][8][4];
    #pragma unroll
    for (int i = 0; i < 2; i++)
        #pragma unroll
        for (int j = 0; j < 8; j++)
            #pragma unroll
            for (int r = 0; r < 4; r++) c[i][j][r] = 0.f;
    float kc[2][4] = {};

    const int a_row = t >> 3, a_c4 = t & 7;
    const int b_k   = t >> 5, b_n4 = t & 31;

    {
        #pragma unroll
        for (int p = 0; p < 4; p++) {
            int row = a_row + p * 32;
            int grow = row0 + row; if (grow >= E) grow = E - 1;
            cp16(&As[row * 36 + a_c4 * 4], A + (size_t)grow * 128 + a_c4 * 4);
        }
        #pragma unroll
        for (int p = 0; p < 4; p++) {
            int kk = b_k + p * 8;
            cp16(&Bs[kk * 132 + b_n4 * 4], B + (size_t)kk * 128 + b_n4 * 4);
        }
        asm volatile("cp.async.commit_group;");
    }

    #pragma unroll
    for (int i = 0; i < 4; i++) {
        const int k0 = i * 32;
        if (i < 3) {
            const int kn = k0 + 32;
            float* Ad = As + ((i + 1) & 1) * 4608;
            float* Bd = Bs + ((i + 1) & 1) * 4224;
            #pragma unroll
            for (int p = 0; p < 4; p++) {
                int row = a_row + p * 32;
                int grow = row0 + row; if (grow >= E) grow = E - 1;
                cp16(&Ad[row * 36 + a_c4 * 4], A + (size_t)grow * 128 + kn + a_c4 * 4);
            }
            #pragma unroll
            for (int p = 0; p < 4; p++) {
                int kk = b_k + p * 8;
                cp16(&Bd[kk * 132 + b_n4 * 4], B + (size_t)(kn + kk) * 128 + b_n4 * 4);
            }
            asm volatile("cp.async.commit_group;");
            asm volatile("cp.async.wait_group 1;");
        } else {
            asm volatile("cp.async.wait_group 0;");
        }
        __syncthreads();

        const float* Ab = As + (i & 1) * 4608;
        const float* Bb = Bs + (i & 1) * 4224;

        #pragma unroll
        for (int ks = 0; ks < 4; ks++) {
            const int kb = ks * 8;
            unsigned af[2][4];
            #pragma unroll
            for (int ma = 0; ma < 2; ma++) {
                int ar = wm * 32 + ma * 16;
                af[ma][0] = f2tf(Ab[(ar + gid    ) * 36 + kb + tid4]);
                af[ma][1] = f2tf(Ab[(ar + gid + 8) * 36 + kb + tid4]);
                af[ma][2] = f2tf(Ab[(ar + gid    ) * 36 + kb + tid4 + 4]);
                af[ma][3] = f2tf(Ab[(ar + gid + 8) * 36 + kb + tid4 + 4]);
            }
            #pragma unroll
            for (int na = 0; na < 8; na++) {
                int bc = wn * 64 + na * 8 + gid;
                unsigned b0 = f2tf(Bb[(kb + tid4    ) * 132 + bc]);
                unsigned b1 = f2tf(Bb[(kb + tid4 + 4) * 132 + bc]);
                #pragma unroll
                for (int ma = 0; ma < 2; ma++) {
                    asm volatile(
                        "mma.sync.aligned.m16n8k8.row.col.f32.tf32.tf32.f32 "
                        "{%0,%1,%2,%3}, {%4,%5,%6,%7}, {%8,%9}, {%0,%1,%2,%3};"
                        : "+f"(c[ma][na][0]), "+f"(c[ma][na][1]),
                          "+f"(c[ma][na][2]), "+f"(c[ma][na][3])
                        : "r"(af[ma][0]), "r"(af[ma][1]), "r"(af[ma][2]), "r"(af[ma][3]),
                          "r"(b0), "r"(b1));
                }
            }
            if (wn == 0) {   // fused kA: B2[k][h] = wkAT[h][k]
                unsigned b0 = f2tf(Wks[gid * 132 + k0 + kb + tid4]);
                unsigned b1 = f2tf(Wks[gid * 132 + k0 + kb + tid4 + 4]);
                #pragma unroll
                for (int ma = 0; ma < 2; ma++) {
                    asm volatile(
                        "mma.sync.aligned.m16n8k8.row.col.f32.tf32.tf32.f32 "
                        "{%0,%1,%2,%3}, {%4,%5,%6,%7}, {%8,%9}, {%0,%1,%2,%3};"
                        : "+f"(kc[ma][0]), "+f"(kc[ma][1]),
                          "+f"(kc[ma][2]), "+f"(kc[ma][3])
                        : "r"(af[ma][0]), "r"(af[ma][1]), "r"(af[ma][2]), "r"(af[ma][3]),
                          "r"(b0), "r"(b1));
                }
            }
        }
        __syncthreads();
    }

    // epilogue: Vh = half(c + bias); pairs (col,col+1) are contiguous -> half2 store
    #pragma unroll
    for (int ma = 0; ma < 2; ma++) {
        int r_base = row0 + wm * 32 + ma * 16 + gid;
        #pragma unroll
        for (int na = 0; na < 8; na++) {
            int col = wn * 64 + na * 8 + 2 * tid4;
            float b0 = bias[col], b1 = bias[col + 1];
            if (r_base < E) {
                __half2 p = __floats2half2_rn(c[ma][na][0] + b0, c[ma][na][1] + b1);
                *(__half2*)(g_Vh + (size_t)r_base * 128 + col) = p;
            }
            if (r_base + 8 < E) {
                __half2 p = __floats2half2_rn(c[ma][na][2] + b0, c[ma][na][3] + b1);
                *(__half2*)(g_Vh + (size_t)(r_base + 8) * 128 + col) = p;
            }
        }
    }
    // epilogue: expk = exp(kA + bkA)
    if (wn == 0) {
        int h0 = 2 * tid4;
        float bk0 = bks[h0], bk1 = bks[h0 + 1];
        #pragma unroll
        for (int ma = 0; ma < 2; ma++) {
            int r = row0 + wm * 32 + ma * 16 + gid;
            if (r < E) {
                g_expk[r * 8 + h0    ] = __expf(kc[ma][0] + bk0);
                g_expk[r * 8 + h0 + 1] = __expf(kc[ma][1] + bk1);
            }
            if (r + 8 < E) {
                g_expk[(r + 8) * 8 + h0    ] = __expf(kc[ma][2] + bk0);
                g_expk[(r + 8) * 8 + h0 + 1] = __expf(kc[ma][3] + bk1);
            }
        }
    }
}

// -------- CSR build --------
__global__ void hist_kernel(const void* __restrict__ idx, int Mp) {
    int m = blockIdx.x * blockDim.x + threadIdx.x;
    if (m >= Mp) return;
    int d = ld_idx(idx, (long long)Mp + m, g_idx64);
    atomicAdd(&g_cnt[d], 1);
}

__global__ void __launch_bounds__(1024) scan1_kernel(int E) {
    int i = blockIdx.x * 1024 + threadIdx.x;
    int c = (i < E) ? g_cnt[i] : 0;
    int lane = threadIdx.x & 31, w = threadIdx.x >> 5;
    int v = c;
    #pragma unroll
    for (int o = 1; o < 32; o <<= 1) {
        int t = __shfl_up_sync(0xffffffffu, v, o);
        if (lane >= o) v += t;
    }
    __shared__ int ws[32];
    if (lane == 31) ws[w] = v;
    __syncthreads();
    if (w == 0) {
        int t = ws[lane];
        #pragma unroll
        for (int o = 1; o < 32; o <<= 1) {
            int u = __shfl_up_sync(0xffffffffu, t, o);
            if (lane >= o) t += u;
        }
        ws[lane] = t;
    }
    __syncthreads();
    int off = (w > 0) ? ws[w - 1] : 0;
    int incl = v + off;
    if (i < E) g_rowptr[i] = incl - c;
    if (threadIdx.x == 1023) g_part[blockIdx.x] = incl;
}

__global__ void scan2_kernel(int NB, int Mp, int E) {
    __shared__ int sh[128];
    int t = threadIdx.x;
    int v = (t < NB) ? g_part[t] : 0;
    sh[t] = v;
    __syncthreads();
    #pragma unroll
    for (int o = 1; o < 128; o <<= 1) {
        int u = (t >= o) ? sh[t - o] : 0;
        __syncthreads();
        sh[t] += u;
        __syncthreads();
    }
    if (t < NB) g_part[t] = sh[t] - v;
    if (t == 0) g_rowptr[E] = Mp;
}

__global__ void scan3_kernel(int E) {
    int i = blockIdx.x * blockDim.x + threadIdx.x;
    if (i >= E) return;
    int r = g_rowptr[i] + g_part[i >> 10];
    g_rowptr[i] = r;
    g_head[i] = r;
}

__global__ void scatter_kernel(const void* __restrict__ idx, int Mp) {
    int m = blockIdx.x * blockDim.x + threadIdx.x;
    if (m >= Mp) return;
    int is64 = g_idx64;
    int s = ld_idx(idx, m, is64);
    int d = ld_idx(idx, (long long)Mp + m, is64);
    int pos = atomicAdd(&g_head[d], 1);
    g_ssort[pos] = s;
}

// -------- K6: gather-only aggregation, warp per destination edge, fp16 Vh ----
__global__ void __launch_bounds__(256) agg_csr_kernel(float* __restrict__ out, int E) {
    int d = (blockIdx.x * 256 + threadIdx.x) >> 5;
    if (d >= E) return;
    int lane = threadIdx.x & 31;
    int h = lane >> 2;
    int beg = g_rowptr[d], end = g_rowptr[d + 1];

    float ax = 0.f, ay = 0.f, az = 0.f, aw = 0.f, sumw = 0.f;
    int s = (beg < end) ? g_ssort[beg] : 0;
    for (int p = beg; p < end; p++) {
        int s_next = (p + 1 < end) ? g_ssort[p + 1] : 0;
        float w = g_expk[s * 8 + h];
        uint2 u = *(const uint2*)(g_Vh + (size_t)s * 128 + lane * 4);
        float2 f01 = __half22float2(*reinterpret_cast<__half2*>(&u.x));
        float2 f23 = __half22float2(*reinterpret_cast<__half2*>(&u.y));
        ax += w * f01.x; ay += w * f01.y; az += w * f23.x; aw += w * f23.y;
        sumw += w;
        s = s_next;
    }
    float inv = __fdividef(1.f, sumw + 1e-16f);
    float4 o = make_float4(ax * inv, ay * inv, az * inv, aw * inv);
    *(float4*)(out + (size_t)d * 128 + lane * 4) = o;
}

extern "C" void kernel_launch(void* const* d_in, const int* in_sizes, int n_in,
                              void* d_out, int out_size) {
    const float* edge_attr = (const float*)d_in[0];
    const void*  idx       = d_in[1];
    // d_in[2]=Wq, d_in[3]=bq dead (softmax shift cancels Q)
    const float* Wk = (const float*)d_in[4];
    const float* bk = (const float*)d_in[5];
    const float* Wv = (const float*)d_in[6];
    const float* bv = (const float*)d_in[7];
    const float* Aw = (const float*)d_in[8];
    float* out = (float*)d_out;

    int E = in_sizes[0] / 128;
    int M = in_sizes[1] / 2;
    if (E > E_CAP) E = E_CAP;
    if (M > M_CAP) M = M_CAP;
    int NB = (E + 1023) / 1024;

    static cudaStream_t s1 = nullptr;
    static cudaEvent_t evFork = nullptr, evJoin = nullptr;
    static bool smem_set = false;
    if (!s1) {
        cudaStreamCreateWithFlags(&s1, cudaStreamNonBlocking);
        cudaEventCreateWithFlags(&evFork, cudaEventDisableTiming);
        cudaEventCreateWithFlags(&evJoin, cudaEventDisableTiming);
    }
    if (!smem_set) {
        cudaFuncSetAttribute(gemm_vh_tf32_kernel,
                             cudaFuncAttributeMaxDynamicSharedMemorySize,
                             SMEM_FLOATS * sizeof(float));
        smem_set = true;
    }

    // fork immediately: chain A never needs the index dtype
    cudaEventRecord(evFork, 0);
    cudaStreamWaitEvent(s1, evFork, 0);

    // chain A (stream 0): prep -> fused GEMM+kA
    prep_kernel<<<1, 128>>>(Wk, bk, Aw);
    gemm_vh_tf32_kernel<<<(E + 127) / 128, 256, SMEM_FLOATS * sizeof(float), 0>>>(
        edge_attr, Wv, bv, E);

    // chain B (stream s1): CSR build
    init_detect_kernel<<<(E + 255) / 256, 256, 0, s1>>>(idx, E);
    hist_kernel<<<(M + 255) / 256, 256, 0, s1>>>(idx, M);
    scan1_kernel<<<NB, 1024, 0, s1>>>(E);
    scan2_kernel<<<1, 128, 0, s1>>>(NB, M, E);
    scan3_kernel<<<(E + 255) / 256, 256, 0, s1>>>(E);
    scatter_kernel<<<(M + 255) / 256, 256, 0, s1>>>(idx, M);
    cudaEventRecord(evJoin, s1);

    // join, then aggregate on stream 0
    cudaStreamWaitEvent(0, evJoin, 0);
    agg_csr_kernel<<<(int)(((long long)E * 32 + 255) / 256), 256>>>(out, E);
}